// round 1
// baseline (speedup 1.0000x reference)
#include <cuda_runtime.h>
#include <cuda_bf16.h>
#include <cstdint>

#define N_NODES 100000
#define N_EDGES 800000
#define H 128

#define TILE_M 128
#define HPITCH 132   // h tile row pitch (floats), 16B-aligned rows
#define WPITCH 133   // transposed W tile pitch (floats), odd-ish to spread banks
#define SMEM_BYTES ((TILE_M * HPITCH + H * WPITCH) * 4)

// Scratch for Wh (forward message transform) and Wth (backward message transform)
__device__ float g_Wh[(size_t)N_NODES * H];
__device__ float g_Wth[(size_t)N_NODES * H];

__device__ __forceinline__ unsigned long long pack2(float lo, float hi) {
    unsigned long long r;
    asm("mov.b64 %0, {%1, %2};" : "=l"(r) : "f"(lo), "f"(hi));
    return r;
}
__device__ __forceinline__ void unpack2(unsigned long long v, float& lo, float& hi) {
    asm("mov.b64 {%0, %1}, %2;" : "=f"(lo), "=f"(hi) : "l"(v));
}
__device__ __forceinline__ void fma2(unsigned long long& acc,
                                     unsigned long long a, unsigned long long b) {
    asm("fma.rn.f32x2 %0, %1, %2, %3;" : "=l"(acc) : "l"(a), "l"(b), "l"(acc));
}

// Computes, for a 128-row tile of h:
//   w=0: g_Wh  = h @ W_w^T  + W_b
//   w=1: d_out = h @ Ws_w^T + Ws_b   (initializes the accumulation buffer)
//   w=2: g_Wth = h @ Wt_w^T + Wt_b
__global__ __launch_bounds__(256, 1)
void gemm3_kernel(const float* __restrict__ h,
                  const float* __restrict__ W0, const float* __restrict__ b0,
                  const float* __restrict__ W1, const float* __restrict__ b1,
                  const float* __restrict__ W2, const float* __restrict__ b2,
                  float* __restrict__ out_self) {
    extern __shared__ float smem[];
    float* hs  = smem;                     // [TILE_M][HPITCH]
    float* Wst = smem + TILE_M * HPITCH;   // [H(k)][WPITCH], Wst[k][o] = W[o][k]

    const int tid = threadIdx.x;
    const int tx = tid & 15;     // col group
    const int ty = tid >> 4;     // row group
    const int rowBase = blockIdx.x * TILE_M;

    // ---- stage h tile (coalesced float4) ----
    #pragma unroll
    for (int it = 0; it < 16; ++it) {
        int idx = tid + it * 256;          // 0..4095 (128 rows x 32 float4)
        int r  = idx >> 5;
        int k4 = idx & 31;
        float4 v = make_float4(0.f, 0.f, 0.f, 0.f);
        int gr = rowBase + r;
        if (gr < N_NODES)
            v = *(const float4*)(h + (size_t)gr * H + k4 * 4);
        *(float4*)(hs + r * HPITCH + k4 * 4) = v;
    }

    #pragma unroll
    for (int w = 0; w < 3; ++w) {
        const float* W    = (w == 0) ? W0 : (w == 1) ? W1 : W2;
        const float* bias = (w == 0) ? b0 : (w == 1) ? b1 : b2;
        float* dst = (w == 0) ? g_Wh : (w == 1) ? out_self : g_Wth;

        __syncthreads();  // previous compute done (also orders hs staging on w=0)
        // ---- stage W transposed into Wst[k][o] ----
        #pragma unroll
        for (int it = 0; it < 16; ++it) {
            int idx = tid + it * 256;      // 0..4095
            int o  = idx >> 5;
            int k4 = idx & 31;
            float4 v = *(const float4*)(W + o * H + k4 * 4);
            Wst[(k4 * 4 + 0) * WPITCH + o] = v.x;
            Wst[(k4 * 4 + 1) * WPITCH + o] = v.y;
            Wst[(k4 * 4 + 2) * WPITCH + o] = v.z;
            Wst[(k4 * 4 + 3) * WPITCH + o] = v.w;
        }
        __syncthreads();

        // ---- compute: rows = ty+16i, col pairs = (tx+32j, tx+32j+16) ----
        unsigned long long acc[8][4];
        #pragma unroll
        for (int i = 0; i < 8; ++i)
            #pragma unroll
            for (int j = 0; j < 4; ++j) acc[i][j] = 0ULL;

        #pragma unroll 4
        for (int k = 0; k < H; ++k) {
            unsigned long long a2[8];
            #pragma unroll
            for (int i = 0; i < 8; ++i) {
                float av = hs[(ty + 16 * i) * HPITCH + k];
                a2[i] = pack2(av, av);
            }
            unsigned long long b2[4];
            #pragma unroll
            for (int j = 0; j < 4; ++j) {
                float blo = Wst[k * WPITCH + tx + 32 * j];
                float bhi = Wst[k * WPITCH + tx + 32 * j + 16];
                b2[j] = pack2(blo, bhi);
            }
            #pragma unroll
            for (int i = 0; i < 8; ++i)
                #pragma unroll
                for (int j = 0; j < 4; ++j)
                    fma2(acc[i][j], a2[i], b2[j]);
        }

        // ---- epilogue: add bias, store ----
        float blo[4], bhi[4];
        #pragma unroll
        for (int j = 0; j < 4; ++j) {
            blo[j] = bias[tx + 32 * j];
            bhi[j] = bias[tx + 32 * j + 16];
        }
        #pragma unroll
        for (int i = 0; i < 8; ++i) {
            int row = rowBase + ty + 16 * i;
            if (row < N_NODES) {
                float* drow = dst + (size_t)row * H;
                #pragma unroll
                for (int j = 0; j < 4; ++j) {
                    float lo, hi;
                    unpack2(acc[i][j], lo, hi);
                    drow[tx + 32 * j]      = lo + blo[j];
                    drow[tx + 32 * j + 16] = hi + bhi[j];
                }
            }
        }
    }
}

// One warp per edge; both aggregation directions in one pass.
// out[src] += Wh[dst];  out[dst] += Wth[src];
__global__ __launch_bounds__(256)
void scatter_kernel(const int* __restrict__ esrc, const int* __restrict__ edst,
                    float* __restrict__ out) {
    int warp = (blockIdx.x * blockDim.x + threadIdx.x) >> 5;
    int lane = threadIdx.x & 31;
    if (warp >= N_EDGES) return;
    int s = __ldg(esrc + warp);
    int d = __ldg(edst + warp);

    const float4 vf = *(const float4*)(g_Wh  + (size_t)d * H + lane * 4);
    const float4 vb = *(const float4*)(g_Wth + (size_t)s * H + lane * 4);

    float* os = out + (size_t)s * H + lane * 4;
    atomicAdd(os + 0, vf.x);
    atomicAdd(os + 1, vf.y);
    atomicAdd(os + 2, vf.z);
    atomicAdd(os + 3, vf.w);

    float* od = out + (size_t)d * H + lane * 4;
    atomicAdd(od + 0, vb.x);
    atomicAdd(od + 1, vb.y);
    atomicAdd(od + 2, vb.z);
    atomicAdd(od + 3, vb.w);
}

__global__ __launch_bounds__(256)
void relu_kernel(float* __restrict__ out) {
    int i = blockIdx.x * blockDim.x + threadIdx.x;
    const int total4 = (N_NODES * H) / 4;
    if (i < total4) {
        float4 v = ((float4*)out)[i];
        v.x = fmaxf(v.x, 0.f);
        v.y = fmaxf(v.y, 0.f);
        v.z = fmaxf(v.z, 0.f);
        v.w = fmaxf(v.w, 0.f);
        ((float4*)out)[i] = v;
    }
}

extern "C" void kernel_launch(void* const* d_in, const int* in_sizes, int n_in,
                              void* d_out, int out_size) {
    const float* h_n   = (const float*)d_in[0];
    const int*   esrc  = (const int*)d_in[1];
    const int*   edst  = (const int*)d_in[2];
    const float* W_w   = (const float*)d_in[3];
    const float* W_b   = (const float*)d_in[4];
    const float* Ws_w  = (const float*)d_in[5];
    const float* Ws_b  = (const float*)d_in[6];
    const float* Wt_w  = (const float*)d_in[7];
    const float* Wt_b  = (const float*)d_in[8];
    float* out = (float*)d_out;

    cudaFuncSetAttribute(gemm3_kernel,
                         cudaFuncAttributeMaxDynamicSharedMemorySize, SMEM_BYTES);

    int gemm_blocks = (N_NODES + TILE_M - 1) / TILE_M;   // 782
    gemm3_kernel<<<gemm_blocks, 256, SMEM_BYTES>>>(
        h_n, W_w, W_b, Ws_w, Ws_b, Wt_w, Wt_b, out);

    int scatter_blocks = (N_EDGES * 32 + 255) / 256;     // 100000
    scatter_kernel<<<scatter_blocks, 256>>>(esrc, edst, out);

    int relu_blocks = ((N_NODES * H) / 4 + 255) / 256;
    relu_kernel<<<relu_blocks, 256>>>(out);
}

// round 2
// speedup vs baseline: 1.4892x; 1.4892x over previous
#include <cuda_runtime.h>
#include <cuda_bf16.h>
#include <cstdint>

#define N_NODES 100000
#define N_EDGES 800000
#define H 128

#define TILE_M 128
#define HPITCH 128   // h tile pitch (compute reads are broadcast; float4 staging conflict-free)
#define WPITCH 132   // transposed W tile pitch
#define SMEM_FLOATS (TILE_M * HPITCH + 2 * H * WPITCH)
#define SMEM_BYTES (SMEM_FLOATS * 4)

// Scratch for Wh (forward message transform) and Wth (backward message transform)
__device__ float g_Wh[(size_t)N_NODES * H];
__device__ float g_Wth[(size_t)N_NODES * H];

__device__ __forceinline__ unsigned long long pack2(float lo, float hi) {
    unsigned long long r;
    asm("mov.b64 %0, {%1, %2};" : "=l"(r) : "f"(lo), "f"(hi));
    return r;
}
__device__ __forceinline__ void unpack2(unsigned long long v, float& lo, float& hi) {
    asm("mov.b64 {%0, %1}, %2;" : "=f"(lo), "=f"(hi) : "l"(v));
}
__device__ __forceinline__ void fma2(unsigned long long& acc,
                                     unsigned long long a, unsigned long long b) {
    asm("fma.rn.f32x2 %0, %1, %2, %3;" : "=l"(acc) : "l"(a), "l"(b), "l"(acc));
}
__device__ __forceinline__ void red4(float* p, float4 v) {
    asm volatile("red.global.add.v4.f32 [%0], {%1, %2, %3, %4};"
                 :: "l"(p), "f"(v.x), "f"(v.y), "f"(v.z), "f"(v.w) : "memory");
}

// For a 128-row tile of h:
//   w=0: g_Wh  = h @ W_w^T  + W_b
//   w=1: d_out = h @ Ws_w^T + Ws_b   (initializes the accumulation buffer)
//   w=2: g_Wth = h @ Wt_w^T + Wt_b
// W tiles are double-buffered: stage of W_{w+1} overlaps compute of W_w.
__global__ __launch_bounds__(256)
void gemm3_kernel(const float* __restrict__ h,
                  const float* __restrict__ W0, const float* __restrict__ b0,
                  const float* __restrict__ W1, const float* __restrict__ b1,
                  const float* __restrict__ W2, const float* __restrict__ b2,
                  float* __restrict__ out_self) {
    extern __shared__ float smem[];
    float* hs = smem;                                  // [TILE_M][HPITCH]
    float* Wb0 = smem + TILE_M * HPITCH;               // [H(k)][WPITCH]
    float* Wb1 = Wb0 + H * WPITCH;

    const int tid = threadIdx.x;
    const int tx = tid & 15;     // col group
    const int ty = tid >> 4;     // row group
    const int rowBase = blockIdx.x * TILE_M;

    const float* Wg[3] = {W0, W1, W2};
    const float* bg[3] = {b0, b1, b2};

    // ---- stage h tile (coalesced float4) ----
    #pragma unroll
    for (int it = 0; it < 16; ++it) {
        int idx = tid + it * 256;          // 0..4095 (128 rows x 32 float4)
        int r  = idx >> 5;
        int k4 = idx & 31;
        float4 v = make_float4(0.f, 0.f, 0.f, 0.f);
        int gr = rowBase + r;
        if (gr < N_NODES)
            v = *(const float4*)(h + (size_t)gr * H + k4 * 4);
        *(float4*)(hs + r * HPITCH + k4 * 4) = v;
    }

    // ---- stage W0 into buffer 0 (transposed: Wst[k][o] = W[o][k]) ----
    {
        const float* W = W0;
        #pragma unroll
        for (int it = 0; it < 16; ++it) {
            int idx = tid + it * 256;
            int o  = idx >> 5;
            int k4 = idx & 31;
            float4 v = *(const float4*)(W + o * H + k4 * 4);
            Wb0[(k4 * 4 + 0) * WPITCH + o] = v.x;
            Wb0[(k4 * 4 + 1) * WPITCH + o] = v.y;
            Wb0[(k4 * 4 + 2) * WPITCH + o] = v.z;
            Wb0[(k4 * 4 + 3) * WPITCH + o] = v.w;
        }
    }
    __syncthreads();

    #pragma unroll
    for (int w = 0; w < 3; ++w) {
        float* Wcur = (w & 1) ? Wb1 : Wb0;
        float* Wnext = (w & 1) ? Wb0 : Wb1;
        const float* bias = bg[w];
        float* dst = (w == 0) ? g_Wh : (w == 1) ? out_self : g_Wth;

        // ---- prefetch-stage next W into the other buffer (overlaps compute) ----
        if (w < 2) {
            const float* W = Wg[w + 1];
            #pragma unroll
            for (int it = 0; it < 16; ++it) {
                int idx = tid + it * 256;
                int o  = idx >> 5;
                int k4 = idx & 31;
                float4 v = *(const float4*)(W + o * H + k4 * 4);
                Wnext[(k4 * 4 + 0) * WPITCH + o] = v.x;
                Wnext[(k4 * 4 + 1) * WPITCH + o] = v.y;
                Wnext[(k4 * 4 + 2) * WPITCH + o] = v.z;
                Wnext[(k4 * 4 + 3) * WPITCH + o] = v.w;
            }
        }

        // ---- compute: rows = ty+16i, col pairs = (tx+32j, tx+32j+16) ----
        unsigned long long acc[8][4];
        #pragma unroll
        for (int i = 0; i < 8; ++i)
            #pragma unroll
            for (int j = 0; j < 4; ++j) acc[i][j] = 0ULL;

        #pragma unroll 4
        for (int k = 0; k < H; ++k) {
            unsigned long long a2[8];
            #pragma unroll
            for (int i = 0; i < 8; ++i) {
                float av = hs[(ty + 16 * i) * HPITCH + k];
                a2[i] = pack2(av, av);
            }
            unsigned long long b2[4];
            #pragma unroll
            for (int j = 0; j < 4; ++j) {
                float blo = Wcur[k * WPITCH + tx + 32 * j];
                float bhi = Wcur[k * WPITCH + tx + 32 * j + 16];
                b2[j] = pack2(blo, bhi);
            }
            #pragma unroll
            for (int i = 0; i < 8; ++i)
                #pragma unroll
                for (int j = 0; j < 4; ++j)
                    fma2(acc[i][j], a2[i], b2[j]);
        }

        // ---- epilogue: add bias, store ----
        float blo[4], bhi[4];
        #pragma unroll
        for (int j = 0; j < 4; ++j) {
            blo[j] = bias[tx + 32 * j];
            bhi[j] = bias[tx + 32 * j + 16];
        }
        #pragma unroll
        for (int i = 0; i < 8; ++i) {
            int row = rowBase + ty + 16 * i;
            if (row < N_NODES) {
                float* drow = dst + (size_t)row * H;
                #pragma unroll
                for (int j = 0; j < 4; ++j) {
                    float lo, hi;
                    unpack2(acc[i][j], lo, hi);
                    drow[tx + 32 * j]      = lo + blo[j];
                    drow[tx + 32 * j + 16] = hi + bhi[j];
                }
            }
        }
        __syncthreads();
    }
}

// One warp per edge; both aggregation directions; 16B vector reduces.
// out[src] += Wh[dst];  out[dst] += Wth[src];
__global__ __launch_bounds__(256)
void scatter_kernel(const int* __restrict__ esrc, const int* __restrict__ edst,
                    float* __restrict__ out) {
    int warp = (blockIdx.x * blockDim.x + threadIdx.x) >> 5;
    int lane = threadIdx.x & 31;
    if (warp >= N_EDGES) return;
    int s = __ldg(esrc + warp);
    int d = __ldg(edst + warp);

    const float4 vf = *(const float4*)(g_Wh  + (size_t)d * H + lane * 4);
    const float4 vb = *(const float4*)(g_Wth + (size_t)s * H + lane * 4);

    red4(out + (size_t)s * H + lane * 4, vf);
    red4(out + (size_t)d * H + lane * 4, vb);
}

__global__ __launch_bounds__(256)
void relu_kernel(float* __restrict__ out) {
    int i = blockIdx.x * blockDim.x + threadIdx.x;
    const int total4 = (N_NODES * H) / 4;
    if (i < total4) {
        float4 v = ((float4*)out)[i];
        v.x = fmaxf(v.x, 0.f);
        v.y = fmaxf(v.y, 0.f);
        v.z = fmaxf(v.z, 0.f);
        v.w = fmaxf(v.w, 0.f);
        ((float4*)out)[i] = v;
    }
}

extern "C" void kernel_launch(void* const* d_in, const int* in_sizes, int n_in,
                              void* d_out, int out_size) {
    const float* h_n   = (const float*)d_in[0];
    const int*   esrc  = (const int*)d_in[1];
    const int*   edst  = (const int*)d_in[2];
    const float* W_w   = (const float*)d_in[3];
    const float* W_b   = (const float*)d_in[4];
    const float* Ws_w  = (const float*)d_in[5];
    const float* Ws_b  = (const float*)d_in[6];
    const float* Wt_w  = (const float*)d_in[7];
    const float* Wt_b  = (const float*)d_in[8];
    float* out = (float*)d_out;

    cudaFuncSetAttribute(gemm3_kernel,
                         cudaFuncAttributeMaxDynamicSharedMemorySize, SMEM_BYTES);

    int gemm_blocks = (N_NODES + TILE_M - 1) / TILE_M;   // 782
    gemm3_kernel<<<gemm_blocks, 256, SMEM_BYTES>>>(
        h_n, W_w, W_b, Ws_w, Ws_b, Wt_w, Wt_b, out);

    int scatter_blocks = (N_EDGES * 32 + 255) / 256;     // 100000
    scatter_kernel<<<scatter_blocks, 256>>>(esrc, edst, out);

    int relu_blocks = ((N_NODES * H) / 4 + 255) / 256;
    relu_kernel<<<relu_blocks, 256>>>(out);
}